// round 1
// baseline (speedup 1.0000x reference)
#include <cuda_runtime.h>
#include <cstdint>
#include <cstdio>

// ============================================================================
// VideokMaXTransformerDecoder — fp32 baseline
//   Stage 1: pixel_space = gelu(BN(W_p1 @ gelu(pixel)))        [128x128x8 SGEMM, fused gelu-in/out]
//   Stage 2: pixel_kv    = BN(W_pkv @ pixel_space)             [128x128x8 SGEMM]
//   Stage 3: query_space = gelu(BN(W_q1 @ query))              [32x64 SGEMM]
//   Stage 4: query_qkv   = BN(W_qkv @ query_space)             [32x64 SGEMM]
//   Stage 5: flash attention, m split into 11 partitions (online softmax partials)
//   Stage 6: reduce partials + BN + gelu -> ret
//   Stage 7: qf  = gelu(query + BN(W_c3 @ ret))                [32x64 SGEMM + residual]
//   Stage 8: ffn = gelu(BN(W_f1 @ qf))                         [32x64 SGEMM]
//   Stage 9: out = gelu(qf + BN(W_f2 @ ffn))                   [32x64 SGEMM + residual]
// ============================================================================

#define NB   8
#define CP   2048
#define HW   4096
#define CQ   256
#define LQ   128
#define NHD  8
#define KD   128
#define VD   256
#define DK_H 16     // KD / NH
#define DV_H 32     // VD / NH
#define BOT  256
#define FFN_C 2048
#define MTOT 4224   // LQ + HW
#define NSPLIT 11
#define CPS 3       // chunks (of 128 m) per split; 11*3*128 = 4224

__device__ __forceinline__ float gelu_f(float x) {
    return 0.5f * x * (1.0f + erff(x * 0.70710678118654752440f));
}

// ---------------- scratch (device globals: no runtime allocation) ----------
__device__ float g_ps  [(size_t)NB * BOT * HW];          // pixel_space  (8,256,4096)
__device__ float g_pkv [(size_t)NB * (KD + VD) * HW];    // pixel_kv     (8,384,4096)
__device__ float g_qs  [NB * BOT * LQ];                  // query_space  (8,256,128)
__device__ float g_qkv [NB * (2 * KD + VD) * LQ];        // query_qkv    (8,512,128)
__device__ float g_ret [NB * VD * LQ];                   // ret          (8,256,128)
__device__ float g_qf  [NB * CQ * LQ];                   // qf           (8,256,128)
__device__ float g_ffn [NB * FFN_C * LQ];                // ffn hidden   (8,2048,128)
__device__ float g_part[(size_t)(NB * NHD) * NSPLIT * 34 * LQ]; // attn partials

// ============================================================================
// Big SGEMM: Y_b = act( S ⊙ (W @ f(X_b)) + B ), tiles 128x128x8, 256 thr, 8x8/thr
//   W: (O,C) row-major.  X: batched (NB, C, Lc).  Requires O%128==0 (or exact
//   gridDim.y*128<=O tiles), C%8==0, Lc%128==0.
// ============================================================================
template<bool GIN, bool GOUT>
__global__ void __launch_bounds__(256, 2) gemm128_kernel(
    const float* __restrict__ W, const float* __restrict__ X,
    const float* __restrict__ S, const float* __restrict__ Bi,
    float* __restrict__ Y, int O, int C, int Lc)
{
    __shared__ float As[8][128];
    __shared__ float Bs[8][128];
    const int tid = threadIdx.x;
    const int m0 = blockIdx.y * 128;
    const int n0 = blockIdx.x * 128;
    const float* Xb = X + (size_t)blockIdx.z * C * Lc;
    float*       Yb = Y + (size_t)blockIdx.z * O * Lc;

    const int arow = tid >> 1, ak = (tid & 1) << 2;
    const int bk   = tid >> 5, bj = (tid & 31) << 2;
    const int tm   = (tid >> 4) << 3, tn = (tid & 15) << 3;

    float acc[8][8];
#pragma unroll
    for (int i = 0; i < 8; i++)
#pragma unroll
        for (int j = 0; j < 8; j++) acc[i][j] = 0.f;

    float4 a4 = *(const float4*)&W[(size_t)(m0 + arow) * C + ak];
    float4 b4 = *(const float4*)&Xb[(size_t)bk * Lc + n0 + bj];

    for (int k0 = 0; k0 < C; k0 += 8) {
        float4 bw = b4;
        if (GIN) { bw.x = gelu_f(bw.x); bw.y = gelu_f(bw.y);
                   bw.z = gelu_f(bw.z); bw.w = gelu_f(bw.w); }
        As[ak + 0][arow] = a4.x; As[ak + 1][arow] = a4.y;
        As[ak + 2][arow] = a4.z; As[ak + 3][arow] = a4.w;
        *(float4*)&Bs[bk][bj] = bw;
        __syncthreads();
        const int k1 = k0 + 8;
        if (k1 < C) {  // prefetch next tiles into registers (hides GMEM latency)
            a4 = *(const float4*)&W[(size_t)(m0 + arow) * C + k1 + ak];
            b4 = *(const float4*)&Xb[(size_t)(k1 + bk) * Lc + n0 + bj];
        }
#pragma unroll
        for (int kk = 0; kk < 8; kk++) {
            float ar[8], br[8];
            *(float4*)&ar[0] = *(const float4*)&As[kk][tm];
            *(float4*)&ar[4] = *(const float4*)&As[kk][tm + 4];
            *(float4*)&br[0] = *(const float4*)&Bs[kk][tn];
            *(float4*)&br[4] = *(const float4*)&Bs[kk][tn + 4];
#pragma unroll
            for (int i = 0; i < 8; i++)
#pragma unroll
                for (int j = 0; j < 8; j++)
                    acc[i][j] = fmaf(ar[i], br[j], acc[i][j]);
        }
        __syncthreads();
    }
#pragma unroll
    for (int i = 0; i < 8; i++) {
        const int m = m0 + tm + i;
        const float sv = S[m], bv = Bi[m];
#pragma unroll
        for (int j4 = 0; j4 < 8; j4 += 4) {
            float4 o;
            o.x = fmaf(acc[i][j4 + 0], sv, bv);
            o.y = fmaf(acc[i][j4 + 1], sv, bv);
            o.z = fmaf(acc[i][j4 + 2], sv, bv);
            o.w = fmaf(acc[i][j4 + 3], sv, bv);
            if (GOUT) { o.x = gelu_f(o.x); o.y = gelu_f(o.y);
                        o.z = gelu_f(o.z); o.w = gelu_f(o.w); }
            *(float4*)&Yb[(size_t)m * Lc + n0 + tn + j4] = o;
        }
    }
}

// ============================================================================
// Skinny SGEMM: tiles 32x64x16, 256 thr, 2x4/thr. Optional residual-then-gelu:
//   Y = act( R + S ⊙ (W @ X) + B )
// Requires O%32==0, C%16==0, Lc%64==0.
// ============================================================================
template<bool GOUT, bool RES>
__global__ void __launch_bounds__(256) gemm_s_kernel(
    const float* __restrict__ W, const float* __restrict__ X,
    const float* __restrict__ S, const float* __restrict__ Bi,
    const float* __restrict__ R,
    float* __restrict__ Y, int O, int C, int Lc)
{
    __shared__ float As[16][32];
    __shared__ float Bs[16][64];
    const int tid = threadIdx.x;
    const int m0 = blockIdx.y * 32;
    const int n0 = blockIdx.x * 64;
    const float* Xb = X + (size_t)blockIdx.z * C * Lc;
    float*       Yb = Y + (size_t)blockIdx.z * O * Lc;

    const int ar_ = tid >> 3, ac = (tid & 7) << 1;
    const int bk  = tid >> 4, bj = (tid & 15) << 2;
    const int tm  = (tid >> 4) << 1, tn = (tid & 15) << 2;

    float acc[2][4] = {{0.f, 0.f, 0.f, 0.f}, {0.f, 0.f, 0.f, 0.f}};
    float2 a2 = *(const float2*)&W[(size_t)(m0 + ar_) * C + ac];
    float4 b4 = *(const float4*)&Xb[(size_t)bk * Lc + n0 + bj];

    for (int k0 = 0; k0 < C; k0 += 16) {
        As[ac + 0][ar_] = a2.x; As[ac + 1][ar_] = a2.y;
        *(float4*)&Bs[bk][bj] = b4;
        __syncthreads();
        const int k1 = k0 + 16;
        if (k1 < C) {
            a2 = *(const float2*)&W[(size_t)(m0 + ar_) * C + k1 + ac];
            b4 = *(const float4*)&Xb[(size_t)(k1 + bk) * Lc + n0 + bj];
        }
#pragma unroll
        for (int kk = 0; kk < 16; kk++) {
            const float a0 = As[kk][tm], a1 = As[kk][tm + 1];
            const float4 bb = *(const float4*)&Bs[kk][tn];
            acc[0][0] = fmaf(a0, bb.x, acc[0][0]); acc[0][1] = fmaf(a0, bb.y, acc[0][1]);
            acc[0][2] = fmaf(a0, bb.z, acc[0][2]); acc[0][3] = fmaf(a0, bb.w, acc[0][3]);
            acc[1][0] = fmaf(a1, bb.x, acc[1][0]); acc[1][1] = fmaf(a1, bb.y, acc[1][1]);
            acc[1][2] = fmaf(a1, bb.z, acc[1][2]); acc[1][3] = fmaf(a1, bb.w, acc[1][3]);
        }
        __syncthreads();
    }
    const float* Rb = RES ? (R + (size_t)blockIdx.z * O * Lc) : nullptr;
#pragma unroll
    for (int i = 0; i < 2; i++) {
        const int m = m0 + tm + i;
        const float sv = S[m], bv = Bi[m];
        float4 o;
        o.x = fmaf(acc[i][0], sv, bv); o.y = fmaf(acc[i][1], sv, bv);
        o.z = fmaf(acc[i][2], sv, bv); o.w = fmaf(acc[i][3], sv, bv);
        if (RES) {
            const float4 r4 = *(const float4*)&Rb[(size_t)m * Lc + n0 + tn];
            o.x += r4.x; o.y += r4.y; o.z += r4.z; o.w += r4.w;
        }
        if (GOUT) { o.x = gelu_f(o.x); o.y = gelu_f(o.y);
                    o.z = gelu_f(o.z); o.w = gelu_f(o.w); }
        *(float4*)&Yb[(size_t)m * Lc + n0 + tn] = o;
    }
}

// ============================================================================
// Flash-style attention, partial over m-splits. grid (NSPLIT, NB*NHD), 128 thr.
// Thread = one query l. Online softmax; rescale only when running max rises.
// Partials: [bh][split][34][128]  rows: 0=max, 1=sum, 2..33=acc[dv]
// ============================================================================
__global__ void __launch_bounds__(128) attn_partial_kernel(
    const float* __restrict__ qkv,   // (8,512,128)
    const float* __restrict__ pkv,   // (8,384,4096)
    const float* __restrict__ ssim_g, const float* __restrict__ bsim_g,
    float* __restrict__ part)
{
    const int split = blockIdx.x;
    const int bh = blockIdx.y;
    const int b = bh >> 3, h = bh & 7;
    const int l = threadIdx.x;
    __shared__ float ks[128][DK_H];
    __shared__ float vs[128][DV_H];
    const float* qkvb = qkv + (size_t)b * (2 * KD + VD) * LQ;
    const float* pkvb = pkv + (size_t)b * (KD + VD) * HW;

    float q[DK_H];
#pragma unroll
    for (int d = 0; d < DK_H; d++) q[d] = qkvb[(h * DK_H + d) * LQ + l];
    const float ssim = ssim_g[h], bsim = bsim_g[h];

    float mrun = -3.0e38f, srun = 0.f;
    float acc[DV_H];
#pragma unroll
    for (int d = 0; d < DV_H; d++) acc[d] = 0.f;

    for (int ci = 0; ci < CPS; ci++) {
        const int cg = split * CPS + ci;
        if (cg == 0) {  // m in [0,128): query-side K/V
#pragma unroll
            for (int d = 0; d < DK_H; d++)
                ks[l][d] = qkvb[(KD + h * DK_H + d) * LQ + l];
#pragma unroll
            for (int d = 0; d < DV_H; d++)
                vs[l][d] = qkvb[(2 * KD + h * DV_H + d) * LQ + l];
        } else {        // pixel-side K/V
            const int p0 = cg * 128 - LQ;
#pragma unroll
            for (int d = 0; d < DK_H; d++)
                ks[l][d] = pkvb[(size_t)(h * DK_H + d) * HW + p0 + l];
#pragma unroll
            for (int d = 0; d < DV_H; d++)
                vs[l][d] = pkvb[(size_t)(KD + h * DV_H + d) * HW + p0 + l];
        }
        __syncthreads();
#pragma unroll 2
        for (int mm = 0; mm < 128; mm++) {
            const float* kr = ks[mm];
            // 4 partial sums to shorten the FMA dependency chain
            float s0 = q[0] * kr[0], s1 = q[1] * kr[1], s2 = q[2] * kr[2], s3 = q[3] * kr[3];
#pragma unroll
            for (int d = 4; d < DK_H; d += 4) {
                s0 = fmaf(q[d + 0], kr[d + 0], s0);
                s1 = fmaf(q[d + 1], kr[d + 1], s1);
                s2 = fmaf(q[d + 2], kr[d + 2], s2);
                s3 = fmaf(q[d + 3], kr[d + 3], s3);
            }
            float sim = fmaf((s0 + s1) + (s2 + s3), ssim, bsim);
            if (sim > mrun) {     // rare: amortized O(log M) per row
                const float r = __expf(mrun - sim);
                srun *= r;
#pragma unroll
                for (int d = 0; d < DV_H; d++) acc[d] *= r;
                mrun = sim;
            }
            const float p = __expf(sim - mrun);
            srun += p;
            const float* vr = vs[mm];
#pragma unroll
            for (int d = 0; d < DV_H; d++) acc[d] = fmaf(p, vr[d], acc[d]);
        }
        __syncthreads();
    }
    float* pp = part + ((size_t)bh * NSPLIT + split) * 34 * LQ;
    pp[l]      = mrun;
    pp[LQ + l] = srun;
#pragma unroll
    for (int d = 0; d < DV_H; d++) pp[(2 + d) * LQ + l] = acc[d];
}

// Combine partials across splits, then BN(s_ret,b_ret)+gelu -> ret (8,256,128)
__global__ void __launch_bounds__(128) attn_reduce_kernel(
    const float* __restrict__ part, const float* __restrict__ sret,
    const float* __restrict__ bret, float* __restrict__ ret)
{
    const int bh = blockIdx.x;
    const int b = bh >> 3, h = bh & 7;
    const int l = threadIdx.x;
    const float* pp = part + (size_t)bh * NSPLIT * 34 * LQ;

    float gm = -3.0e38f;
    float mx[NSPLIT];
#pragma unroll
    for (int i = 0; i < NSPLIT; i++) {
        mx[i] = pp[i * 34 * LQ + l];
        gm = fmaxf(gm, mx[i]);
    }
    float tot = 0.f, acc[DV_H];
#pragma unroll
    for (int d = 0; d < DV_H; d++) acc[d] = 0.f;
#pragma unroll
    for (int i = 0; i < NSPLIT; i++) {
        const float w = __expf(mx[i] - gm);
        tot = fmaf(w, pp[i * 34 * LQ + LQ + l], tot);
#pragma unroll
        for (int d = 0; d < DV_H; d++)
            acc[d] = fmaf(w, pp[i * 34 * LQ + (2 + d) * LQ + l], acc[d]);
    }
    const float inv = 1.f / tot;
#pragma unroll
    for (int d = 0; d < DV_H; d++) {
        const int c = h * DV_H + d;
        const float v = fmaf(acc[d] * inv, sret[c], bret[c]);
        ret[((size_t)b * VD + c) * LQ + l] = gelu_f(v);
    }
}

// ============================================================================
extern "C" void kernel_launch(void* const* d_in, const int* in_sizes, int n_in,
                              void* d_out, int out_size)
{
    const float* pf    = (const float*)d_in[0];
    const float* qfeat = (const float*)d_in[1];
    const float* w_q1  = (const float*)d_in[2];
    const float* s_q1  = (const float*)d_in[3];
    const float* b_q1  = (const float*)d_in[4];
    const float* w_p1  = (const float*)d_in[5];
    const float* s_p1  = (const float*)d_in[6];
    const float* b_p1  = (const float*)d_in[7];
    const float* w_qkv = (const float*)d_in[8];
    const float* s_qkv = (const float*)d_in[9];
    const float* b_qkv = (const float*)d_in[10];
    const float* w_pkv = (const float*)d_in[11];
    const float* s_pkv = (const float*)d_in[12];
    const float* b_pkv = (const float*)d_in[13];
    const float* s_sim = (const float*)d_in[14];
    const float* b_sim = (const float*)d_in[15];
    const float* s_ret = (const float*)d_in[16];
    const float* b_ret = (const float*)d_in[17];
    const float* w_c3  = (const float*)d_in[18];
    const float* s_c3  = (const float*)d_in[19];
    const float* b_c3  = (const float*)d_in[20];
    const float* w_f1  = (const float*)d_in[21];
    const float* s_f1  = (const float*)d_in[22];
    const float* b_f1  = (const float*)d_in[23];
    const float* w_f2  = (const float*)d_in[24];
    const float* s_f2  = (const float*)d_in[25];
    const float* b_f2  = (const float*)d_in[26];
    float* out = (float*)d_out;

    float *ps, *pkv, *qs, *qkv, *retb, *qfb, *ffn, *partb;
    cudaGetSymbolAddress((void**)&ps,    g_ps);
    cudaGetSymbolAddress((void**)&pkv,   g_pkv);
    cudaGetSymbolAddress((void**)&qs,    g_qs);
    cudaGetSymbolAddress((void**)&qkv,   g_qkv);
    cudaGetSymbolAddress((void**)&retb,  g_ret);
    cudaGetSymbolAddress((void**)&qfb,   g_qf);
    cudaGetSymbolAddress((void**)&ffn,   g_ffn);
    cudaGetSymbolAddress((void**)&partb, g_part);

    // 1) pixel_space = gelu(BN(W_p1 @ gelu(pixel)))   (8,256,4096)
    gemm128_kernel<true, true><<<dim3(HW / 128, BOT / 128, NB), 256>>>(
        w_p1, pf, s_p1, b_p1, ps, BOT, CP, HW);
    // 2) pixel_kv = BN(W_pkv @ pixel_space)           (8,384,4096)
    gemm128_kernel<false, false><<<dim3(HW / 128, (KD + VD) / 128, NB), 256>>>(
        w_pkv, ps, s_pkv, b_pkv, pkv, KD + VD, BOT, HW);
    // 3) query_space = gelu(BN(W_q1 @ query))         (8,256,128)
    gemm_s_kernel<true, false><<<dim3(LQ / 64, BOT / 32, NB), 256>>>(
        w_q1, qfeat, s_q1, b_q1, nullptr, qs, BOT, CQ, LQ);
    // 4) query_qkv = BN(W_qkv @ query_space)          (8,512,128)
    gemm_s_kernel<false, false><<<dim3(LQ / 64, (2 * KD + VD) / 32, NB), 256>>>(
        w_qkv, qs, s_qkv, b_qkv, nullptr, qkv, 2 * KD + VD, BOT, LQ);
    // 5) attention partials (online softmax over m-splits)
    attn_partial_kernel<<<dim3(NSPLIT, NB * NHD), 128>>>(qkv, pkv, s_sim, b_sim, partb);
    // 6) reduce + BN + gelu -> ret                    (8,256,128)
    attn_reduce_kernel<<<NB * NHD, 128>>>(partb, s_ret, b_ret, retb);
    // 7) qf = gelu(query + BN(W_c3 @ ret))            (8,256,128)
    gemm_s_kernel<true, true><<<dim3(LQ / 64, CQ / 32, NB), 256>>>(
        w_c3, retb, s_c3, b_c3, qfeat, qfb, CQ, VD, LQ);
    // 8) ffn = gelu(BN(W_f1 @ qf))                    (8,2048,128)
    gemm_s_kernel<true, false><<<dim3(LQ / 64, FFN_C / 32, NB), 256>>>(
        w_f1, qfb, s_f1, b_f1, nullptr, ffn, FFN_C, CQ, LQ);
    // 9) out = gelu(qf + BN(W_f2 @ ffn))              (8,256,128)
    gemm_s_kernel<true, true><<<dim3(LQ / 64, CQ / 32, NB), 256>>>(
        w_f2, ffn, s_f2, b_f2, qfb, out, CQ, FFN_C, LQ);
}

// round 5
// speedup vs baseline: 1.4669x; 1.4669x over previous
#include <cuda_runtime.h>
#include <cuda_bf16.h>
#include <cstdint>

// ============================================================================
// VideokMaXTransformerDecoder — R5 (identical resubmit of R3/R4; both died to
// "container failed twice" broker infra errors, same as the R0 stub round.
// Source re-audited: no divergent barriers, no unbounded loops, no OOB.)
// Stages 1&2 via mma.sync bf16 (split-bf16, fp32 accum, 3 passes).
// tcgen05 unavailable: harness compiles -arch=sm_100 (no 'a' suffix).
// ============================================================================

#define NB   8
#define CP   2048
#define HW   4096
#define CQ   256
#define LQ   128
#define NHD  8
#define KD   128
#define VD   256
#define DK_H 16
#define DV_H 32
#define BOT  256
#define FFN_C 2048
#define NSPLIT 11
#define CPS 3
#define KC   32        // K chunk (bf16 elems) for the mma kernel

__device__ __forceinline__ float gelu_f(float x) {
    return 0.5f * x * (1.0f + erff(x * 0.70710678118654752440f));
}

// ---------------- scratch ----------
__device__ float g_ps  [(size_t)NB * BOT * HW];
__device__ float g_pkv [(size_t)NB * (KD + VD) * HW];
__device__ float g_qs  [NB * BOT * LQ];
__device__ float g_qkv [NB * (2 * KD + VD) * LQ];
__device__ float g_ret [NB * VD * LQ];
__device__ float g_qf  [NB * CQ * LQ];
__device__ float g_ffn [NB * FFN_C * LQ];
__device__ float g_part[(size_t)(NB * NHD) * NSPLIT * 34 * LQ];

// ======================= helpers =====================================
__device__ __forceinline__ uint32_t smem_u32(const void* p) {
    uint32_t a;
    asm("{ .reg .u64 t; cvta.to.shared.u64 t, %1; cvt.u32.u64 %0, t; }" : "=r"(a) : "l"(p));
    return a;
}

#define LDSM4(r0, r1, r2, r3, addr)                                              \
    asm volatile("ldmatrix.sync.aligned.m8n8.x4.shared.b16 {%0,%1,%2,%3}, [%4];" \
        : "=r"(r0), "=r"(r1), "=r"(r2), "=r"(r3) : "r"(addr))
#define LDSM2T(r0, r1, addr)                                                     \
    asm volatile("ldmatrix.sync.aligned.m8n8.x2.trans.shared.b16 {%0,%1}, [%2];" \
        : "=r"(r0), "=r"(r1) : "r"(addr))
#define MMA16816(d, a, b)                                                        \
    asm volatile("mma.sync.aligned.m16n8k16.row.col.f32.bf16.bf16.f32 "          \
        "{%0,%1,%2,%3}, {%4,%5,%6,%7}, {%8,%9}, {%0,%1,%2,%3};"                  \
        : "+f"((d)[0]), "+f"((d)[1]), "+f"((d)[2]), "+f"((d)[3])                 \
        : "r"((a)[0]), "r"((a)[1]), "r"((a)[2]), "r"((a)[3]),                    \
          "r"((b)[0]), "r"((b)[1]))

// split fp32 -> bf16 hi/lo, two elems packed into u32s
__device__ __forceinline__ void split2(float x0, float x1, uint32_t& hi, uint32_t& lo) {
    unsigned short h0 = __bfloat16_as_ushort(__float2bfloat16_rn(x0));
    unsigned short h1 = __bfloat16_as_ushort(__float2bfloat16_rn(x1));
    float f0 = __uint_as_float((uint32_t)h0 << 16);
    float f1 = __uint_as_float((uint32_t)h1 << 16);
    unsigned short l0 = __bfloat16_as_ushort(__float2bfloat16_rn(x0 - f0));
    unsigned short l1 = __bfloat16_as_ushort(__float2bfloat16_rn(x1 - f1));
    hi = ((uint32_t)h1 << 16) | h0;
    lo = ((uint32_t)l1 << 16) | l0;
}
__device__ __forceinline__ void sts2(uint32_t addr, uint32_t u0, uint32_t u1) {
    asm volatile("st.shared.v2.u32 [%0], {%1, %2};" :: "r"(addr), "r"(u0), "r"(u1));
}

// A tile: 128 x KC bf16, row stride 40 (pad 8) -> 80B rows, ldmatrix conflict-free
// B tile: KC x 128 bf16, row stride 136 (pad 8) -> 272B rows, conflict-free
#define ASTR 40
#define BSTR 136

// ============================================================================
// mma.sync GEMM: Y_b = act( S*(W @ f(X_b)) + B ).  Tile M=128,N=128,K=KC.
//   8 warps: warp (wm,wn) owns 64x32; 4x4 fragments of m16n8k16.
// ============================================================================
template<bool GIN, bool GOUT>
__global__ void __launch_bounds__(256, 1) gemm_mma_kernel(
    const float* __restrict__ W, const float* __restrict__ X,
    const float* __restrict__ S, const float* __restrict__ Bi,
    float* __restrict__ Y, int O, int C, int Ntot)
{
    __shared__ __align__(16) __nv_bfloat16 Ahi[128][ASTR];
    __shared__ __align__(16) __nv_bfloat16 Alo[128][ASTR];
    __shared__ __align__(16) __nv_bfloat16 Bhi[KC][BSTR];
    __shared__ __align__(16) __nv_bfloat16 Blo[KC][BSTR];

    const int tid = threadIdx.x;
    const int lane = tid & 31, wid = tid >> 5;
    const int wm = wid & 1, wn = wid >> 1;    // 2 x 4 warp grid
    const int m0 = blockIdx.y * 128;
    const int n0 = blockIdx.x * 128;
    const float* Xb = X + (size_t)blockIdx.z * C * Ntot;
    float*       Yb = Y + (size_t)blockIdx.z * O * Ntot;

    const uint32_t aHiB = smem_u32(Ahi), aLoB = smem_u32(Alo);
    const uint32_t bHiB = smem_u32(Bhi), bLoB = smem_u32(Blo);

    float acc[4][4][4];
#pragma unroll
    for (int i = 0; i < 4; i++)
#pragma unroll
        for (int j = 0; j < 4; j++)
#pragma unroll
            for (int r = 0; r < 4; r++) acc[i][j][r] = 0.f;

    // per-thread load coords
    const int arw = tid >> 3, ac4 = (tid & 7) << 2;     // +32 rows per t-step
    const int brw = tid >> 5, bj4 = (tid & 31) << 2;    // +8 rows per t-step

    float4 pa[4], pb[4];
#pragma unroll
    for (int t = 0; t < 4; t++) {
        pa[t] = *(const float4*)&W[(size_t)(m0 + arw + 32 * t) * C + ac4];
        pb[t] = *(const float4*)&Xb[(size_t)(brw + 8 * t) * Ntot + n0 + bj4];
    }

    const int NCH = C / KC;
    for (int c = 0; c < NCH; c++) {
        // ---- convert + store current chunk
#pragma unroll
        for (int t = 0; t < 4; t++) {
            float4 v = pa[t];
            uint32_t h0, l0, h1, l1;
            split2(v.x, v.y, h0, l0);
            split2(v.z, v.w, h1, l1);
            const uint32_t off = ((uint32_t)(arw + 32 * t) * ASTR + ac4) * 2;
            sts2(aHiB + off, h0, h1);
            sts2(aLoB + off, l0, l1);
        }
#pragma unroll
        for (int t = 0; t < 4; t++) {
            float4 v = pb[t];
            if (GIN) { v.x = gelu_f(v.x); v.y = gelu_f(v.y);
                       v.z = gelu_f(v.z); v.w = gelu_f(v.w); }
            uint32_t h0, l0, h1, l1;
            split2(v.x, v.y, h0, l0);
            split2(v.z, v.w, h1, l1);
            const uint32_t off = ((uint32_t)(brw + 8 * t) * BSTR + bj4) * 2;
            sts2(bHiB + off, h0, h1);
            sts2(bLoB + off, l0, l1);
        }
        __syncthreads();

        // ---- prefetch next chunk (LDGs fly under the MMAs below)
        if (c + 1 < NCH) {
            const int k0 = (c + 1) * KC;
#pragma unroll
            for (int t = 0; t < 4; t++) {
                pa[t] = *(const float4*)&W[(size_t)(m0 + arw + 32 * t) * C + k0 + ac4];
                pb[t] = *(const float4*)&Xb[(size_t)(k0 + brw + 8 * t) * Ntot + n0 + bj4];
            }
        }

        // ---- compute: two k16 steps
#pragma unroll
        for (int k16 = 0; k16 < KC; k16 += 16) {
            uint32_t ah[4][4], al[4][4], bh[4][2], bl[4][2];
            const uint32_t arow = (uint32_t)(wm * 64 + (lane & 15));
            const uint32_t acol = (uint32_t)(k16 + ((lane >> 4) << 3));
#pragma unroll
            for (int mt = 0; mt < 4; mt++) {
                const uint32_t off = ((arow + mt * 16) * ASTR + acol) * 2;
                LDSM4(ah[mt][0], ah[mt][1], ah[mt][2], ah[mt][3], aHiB + off);
                LDSM4(al[mt][0], al[mt][1], al[mt][2], al[mt][3], aLoB + off);
            }
            const uint32_t brow = (uint32_t)(k16 + (lane & 15));
#pragma unroll
            for (int nt = 0; nt < 4; nt++) {
                const uint32_t off = (brow * BSTR + wn * 32 + nt * 8) * 2;
                LDSM2T(bh[nt][0], bh[nt][1], bHiB + off);
                LDSM2T(bl[nt][0], bl[nt][1], bLoB + off);
            }
#pragma unroll
            for (int mt = 0; mt < 4; mt++)
#pragma unroll
                for (int nt = 0; nt < 4; nt++) {
                    MMA16816(acc[mt][nt], ah[mt], bh[nt]);
                    MMA16816(acc[mt][nt], ah[mt], bl[nt]);
                    MMA16816(acc[mt][nt], al[mt], bh[nt]);
                }
        }
        __syncthreads();
    }

    // ---- epilogue: BN (+gelu), store. D frag: row=(lane>>2)+8*half, col=(lane&3)*2
#pragma unroll
    for (int mt = 0; mt < 4; mt++) {
        const int mb = m0 + wm * 64 + mt * 16 + (lane >> 2);
#pragma unroll
        for (int half = 0; half < 2; half++) {
            const int m = mb + 8 * half;
            const float sv = S[m], bv = Bi[m];
#pragma unroll
            for (int nt = 0; nt < 4; nt++) {
                const int col = n0 + wn * 32 + nt * 8 + ((lane & 3) << 1);
                float2 o;
                o.x = fmaf(acc[mt][nt][2 * half + 0], sv, bv);
                o.y = fmaf(acc[mt][nt][2 * half + 1], sv, bv);
                if (GOUT) { o.x = gelu_f(o.x); o.y = gelu_f(o.y); }
                *(float2*)&Yb[(size_t)m * Ntot + col] = o;
            }
        }
    }
}

// ============================================================================
// Skinny SGEMM (unchanged)
// ============================================================================
template<bool GOUT, bool RES>
__global__ void __launch_bounds__(256) gemm_s_kernel(
    const float* __restrict__ W, const float* __restrict__ X,
    const float* __restrict__ S, const float* __restrict__ Bi,
    const float* __restrict__ R,
    float* __restrict__ Y, int O, int C, int Lc)
{
    __shared__ float As[16][32];
    __shared__ float Bs[16][64];
    const int tid = threadIdx.x;
    const int m0 = blockIdx.y * 32;
    const int n0 = blockIdx.x * 64;
    const float* Xb = X + (size_t)blockIdx.z * C * Lc;
    float*       Yb = Y + (size_t)blockIdx.z * O * Lc;

    const int ar_ = tid >> 3, ac = (tid & 7) << 1;
    const int bk  = tid >> 4, bj = (tid & 15) << 2;
    const int tm  = (tid >> 4) << 1, tn = (tid & 15) << 2;

    float acc[2][4] = {{0.f, 0.f, 0.f, 0.f}, {0.f, 0.f, 0.f, 0.f}};
    float2 a2 = *(const float2*)&W[(size_t)(m0 + ar_) * C + ac];
    float4 b4 = *(const float4*)&Xb[(size_t)bk * Lc + n0 + bj];

    for (int k0 = 0; k0 < C; k0 += 16) {
        As[ac + 0][ar_] = a2.x; As[ac + 1][ar_] = a2.y;
        *(float4*)&Bs[bk][bj] = b4;
        __syncthreads();
        const int k1 = k0 + 16;
        if (k1 < C) {
            a2 = *(const float2*)&W[(size_t)(m0 + ar_) * C + k1 + ac];
            b4 = *(const float4*)&Xb[(size_t)(k1 + bk) * Lc + n0 + bj];
        }
#pragma unroll
        for (int kk = 0; kk < 16; kk++) {
            const float a0 = As[kk][tm], a1 = As[kk][tm + 1];
            const float4 bb = *(const float4*)&Bs[kk][tn];
            acc[0][0] = fmaf(a0, bb.x, acc[0][0]); acc[0][1] = fmaf(a0, bb.y, acc[0][1]);
            acc[0][2] = fmaf(a0, bb.z, acc[0][2]); acc[0][3] = fmaf(a0, bb.w, acc[0][3]);
            acc[1][0] = fmaf(a1, bb.x, acc[1][0]); acc[1][1] = fmaf(a1, bb.y, acc[1][1]);
            acc[1][2] = fmaf(a1, bb.z, acc[1][2]); acc[1][3] = fmaf(a1, bb.w, acc[1][3]);
        }
        __syncthreads();
    }
    const float* Rb = RES ? (R + (size_t)blockIdx.z * O * Lc) : nullptr;
#pragma unroll
    for (int i = 0; i < 2; i++) {
        const int m = m0 + tm + i;
        const float sv = S[m], bv = Bi[m];
        float4 o;
        o.x = fmaf(acc[i][0], sv, bv); o.y = fmaf(acc[i][1], sv, bv);
        o.z = fmaf(acc[i][2], sv, bv); o.w = fmaf(acc[i][3], sv, bv);
        if (RES) {
            const float4 r4 = *(const float4*)&Rb[(size_t)m * Lc + n0 + tn];
            o.x += r4.x; o.y += r4.y; o.z += r4.z; o.w += r4.w;
        }
        if (GOUT) { o.x = gelu_f(o.x); o.y = gelu_f(o.y);
                    o.z = gelu_f(o.z); o.w = gelu_f(o.w); }
        *(float4*)&Yb[(size_t)m * Lc + n0 + tn] = o;
    }
}

// ============================================================================
// Attention (unchanged)
// ============================================================================
__global__ void __launch_bounds__(128) attn_partial_kernel(
    const float* __restrict__ qkv, const float* __restrict__ pkv,
    const float* __restrict__ ssim_g, const float* __restrict__ bsim_g,
    float* __restrict__ part)
{
    const int split = blockIdx.x;
    const int bh = blockIdx.y;
    const int b = bh >> 3, h = bh & 7;
    const int l = threadIdx.x;
    __shared__ float ks[128][DK_H];
    __shared__ float vs[128][DV_H];
    const float* qkvb = qkv + (size_t)b * (2 * KD + VD) * LQ;
    const float* pkvb = pkv + (size_t)b * (KD + VD) * HW;

    float q[DK_H];
#pragma unroll
    for (int d = 0; d < DK_H; d++) q[d] = qkvb[(h * DK_H + d) * LQ + l];
    const float ssim = ssim_g[h], bsim = bsim_g[h];

    float mrun = -3.0e38f, srun = 0.f;
    float acc[DV_H];
#pragma unroll
    for (int d = 0; d < DV_H; d++) acc[d] = 0.f;

    for (int ci = 0; ci < CPS; ci++) {
        const int cg = split * CPS + ci;
        if (cg == 0) {
#pragma unroll
            for (int d = 0; d < DK_H; d++)
                ks[l][d] = qkvb[(KD + h * DK_H + d) * LQ + l];
#pragma unroll
            for (int d = 0; d < DV_H; d++)
                vs[l][d] = qkvb[(2 * KD + h * DV_H + d) * LQ + l];
        } else {
            const int p0 = cg * 128 - LQ;
#pragma unroll
            for (int d = 0; d < DK_H; d++)
                ks[l][d] = pkvb[(size_t)(h * DK_H + d) * HW + p0 + l];
#pragma unroll
            for (int d = 0; d < DV_H; d++)
                vs[l][d] = pkvb[(size_t)(KD + h * DV_H + d) * HW + p0 + l];
        }
        __syncthreads();
#pragma unroll 2
        for (int mm = 0; mm < 128; mm++) {
            const float* kr = ks[mm];
            float s0 = q[0] * kr[0], s1 = q[1] * kr[1], s2 = q[2] * kr[2], s3 = q[3] * kr[3];
#pragma unroll
            for (int d = 4; d < DK_H; d += 4) {
                s0 = fmaf(q[d + 0], kr[d + 0], s0);
                s1 = fmaf(q[d + 1], kr[d + 1], s1);
                s2 = fmaf(q[d + 2], kr[d + 2], s2);
                s3 = fmaf(q[d + 3], kr[d + 3], s3);
            }
            float sim = fmaf((s0 + s1) + (s2 + s3), ssim, bsim);
            if (sim > mrun) {
                const float r = __expf(mrun - sim);
                srun *= r;
#pragma unroll
                for (int d = 0; d < DV_H; d++) acc[d] *= r;
                mrun = sim;
            }
            const float p = __expf(sim - mrun);
            srun += p;
            const float* vr = vs[mm];
#pragma unroll
            for (int d = 0; d < DV_H; d++) acc[d] = fmaf(p, vr[d], acc[d]);
        }
        __syncthreads();
    }
    float* pp = part + ((size_t)bh * NSPLIT + split) * 34 * LQ;
    pp[l]      = mrun;
    pp[LQ + l] = srun;
#pragma unroll
    for (int d = 0; d < DV_H; d++) pp[(2 + d) * LQ + l] = acc[d];
}

__global__ void __launch_bounds__(128) attn_reduce_kernel(
    const float* __restrict__ part, const float* __restrict__ sret,
    const float* __restrict__ bret, float* __restrict__ ret)
{
    const int bh = blockIdx.x;
    const int b = bh >> 3, h = bh & 7;
    const int l = threadIdx.x;
    const float* pp = part + (size_t)bh * NSPLIT * 34 * LQ;

    float gm = -3.0e38f;
    float mx[NSPLIT];
#pragma unroll
    for (int i = 0; i < NSPLIT; i++) {
        mx[i] = pp[i * 34 * LQ + l];
        gm = fmaxf(gm, mx[i]);
    }
    float tot = 0.f, acc[DV_H];
#pragma unroll
    for (int d = 0; d < DV_H; d++) acc[d] = 0.f;
#pragma unroll
    for (int i = 0; i < NSPLIT; i++) {
        const float w = __expf(mx[i] - gm);
        tot = fmaf(w, pp[i * 34 * LQ + LQ + l], tot);
#pragma unroll
        for (int d = 0; d < DV_H; d++)
            acc[d] = fmaf(w, pp[i * 34 * LQ + (2 + d) * LQ + l], acc[d]);
    }
    const float inv = 1.f / tot;
#pragma unroll
    for (int d = 0; d < DV_H; d++) {
        const int c = h * DV_H + d;
        const float v = fmaf(acc[d] * inv, sret[c], bret[c]);
        ret[((size_t)b * VD + c) * LQ + l] = gelu_f(v);
    }
}

// ============================================================================
extern "C" void kernel_launch(void* const* d_in, const int* in_sizes, int n_in,
                              void* d_out, int out_size)
{
    const float* pf    = (const float*)d_in[0];
    const float* qfeat = (const float*)d_in[1];
    const float* w_q1  = (const float*)d_in[2];
    const float* s_q1  = (const float*)d_in[3];
    const float* b_q1  = (const float*)d_in[4];
    const float* w_p1  = (const float*)d_in[5];
    const float* s_p1  = (const float*)d_in[6];
    const float* b_p1  = (const float*)d_in[7];
    const float* w_qkv = (const float*)d_in[8];
    const float* s_qkv = (const float*)d_in[9];
    const float* b_qkv = (const float*)d_in[10];
    const float* w_pkv = (const float*)d_in[11];
    const float* s_pkv = (const float*)d_in[12];
    const float* b_pkv = (const float*)d_in[13];
    const float* s_sim = (const float*)d_in[14];
    const float* b_sim = (const float*)d_in[15];
    const float* s_ret = (const float*)d_in[16];
    const float* b_ret = (const float*)d_in[17];
    const float* w_c3  = (const float*)d_in[18];
    const float* s_c3  = (const float*)d_in[19];
    const float* b_c3  = (const float*)d_in[20];
    const float* w_f1  = (const float*)d_in[21];
    const float* s_f1  = (const float*)d_in[22];
    const float* b_f1  = (const float*)d_in[23];
    const float* w_f2  = (const float*)d_in[24];
    const float* s_f2  = (const float*)d_in[25];
    const float* b_f2  = (const float*)d_in[26];
    float* out = (float*)d_out;

    float *ps, *pkv, *qs, *qkv, *retb, *qfb, *ffn, *partb;
    cudaGetSymbolAddress((void**)&ps,    g_ps);
    cudaGetSymbolAddress((void**)&pkv,   g_pkv);
    cudaGetSymbolAddress((void**)&qs,    g_qs);
    cudaGetSymbolAddress((void**)&qkv,   g_qkv);
    cudaGetSymbolAddress((void**)&retb,  g_ret);
    cudaGetSymbolAddress((void**)&qfb,   g_qf);
    cudaGetSymbolAddress((void**)&ffn,   g_ffn);
    cudaGetSymbolAddress((void**)&partb, g_part);

    // 1) pixel_space = gelu(BN(W_p1 @ gelu(pixel)))   (8,256,4096)  [mma.sync]
    gemm_mma_kernel<true, true><<<dim3(HW / 128, BOT / 128, NB), 256>>>(
        w_p1, pf, s_p1, b_p1, ps, BOT, CP, HW);
    // 2) pixel_kv = BN(W_pkv @ pixel_space)           (8,384,4096)  [mma.sync]
    gemm_mma_kernel<false, false><<<dim3(HW / 128, (KD + VD) / 128, NB), 256>>>(
        w_pkv, ps, s_pkv, b_pkv, pkv, KD + VD, BOT, HW);
    // 3) query_space = gelu(BN(W_q1 @ query))         (8,256,128)
    gemm_s_kernel<true, false><<<dim3(LQ / 64, BOT / 32, NB), 256>>>(
        w_q1, qfeat, s_q1, b_q1, nullptr, qs, BOT, CQ, LQ);
    // 4) query_qkv = BN(W_qkv @ query_space)          (8,512,128)
    gemm_s_kernel<false, false><<<dim3(LQ / 64, (2 * KD + VD) / 32, NB), 256>>>(
        w_qkv, qs, s_qkv, b_qkv, nullptr, qkv, 2 * KD + VD, BOT, LQ);
    // 5) attention partials
    attn_partial_kernel<<<dim3(NSPLIT, NB * NHD), 128>>>(qkv, pkv, s_sim, b_sim, partb);
    // 6) reduce + BN + gelu -> ret
    attn_reduce_kernel<<<NB * NHD, 128>>>(partb, s_ret, b_ret, retb);
    // 7) qf = gelu(query + BN(W_c3 @ ret))
    gemm_s_kernel<true, true><<<dim3(LQ / 64, CQ / 32, NB), 256>>>(
        w_c3, retb, s_c3, b_c3, qfeat, qfb, CQ, VD, LQ);
    // 8) ffn = gelu(BN(W_f1 @ qf))
    gemm_s_kernel<true, false><<<dim3(LQ / 64, FFN_C / 32, NB), 256>>>(
        w_f1, qfb, s_f1, b_f1, nullptr, ffn, FFN_C, CQ, LQ);
    // 9) out = gelu(qf + BN(W_f2 @ ffn))
    gemm_s_kernel<true, true><<<dim3(LQ / 64, CQ / 32, NB), 256>>>(
        w_f2, ffn, s_f2, b_f2, qfb, out, CQ, FFN_C, LQ);
}